// round 4
// baseline (speedup 1.0000x reference)
#include <cuda_runtime.h>
#include <cstdint>

#define NIN   1024
#define NOUT  4096
#define NROWS 64            // BATCH*FEAT
#define COLT  128           // columns per k_pool CTA
#define ROWT  16            // rows per k_pool CTA
#define XS    1028          // padded smem row stride (floats)
#define OSS   132           // padded output-stage stride (floats)

// CSC scratch: per-column nonzero-row index lists + counts.
__device__ unsigned short g_idx[(size_t)NOUT * NIN];  // 8 MB (full capacity, can't overflow)
__device__ int            g_cnt[NOUT];

// ---------------------------------------------------------------------------
// Kernel 0: zero the per-column counters (device globals persist across graph
// replays, so this must run every launch).
// ---------------------------------------------------------------------------
__global__ void k_zero()
{
    g_cnt[blockIdx.x * 1024 + threadIdx.x] = 0;
}

// ---------------------------------------------------------------------------
// Kernel 1: scan B (exact 0.0f/1.0f) -> CSC index lists.
// grid = (NOUT/32, 2), 256 threads. Warp w handles 2 n-groups (32 rows each):
// g = by*16 + w*2 + {0,1}. All 16 LDG.128 issued up front for MLP.
// Lane map per group: r0 = lane>>3 row phase, cq = lane&7 column quartet.
// Bit = fp32 exponent bit 23 (1.0f has it set, 0.0f doesn't).
// ---------------------------------------------------------------------------
__device__ __forceinline__ void emit_cols(unsigned p0, unsigned p1, unsigned p2,
                                          unsigned p3, int colbase, int n0)
{
    unsigned ps[4] = {p0, p1, p2, p3};
    #pragma unroll
    for (int j = 0; j < 4; j++) {
        unsigned pv = ps[j];
        int pc = __popc(pv);
        if (pc) {
            const int col = colbase + j;
            int slot = atomicAdd(&g_cnt[col], pc);
            unsigned short* op = g_idx + (size_t)col * NIN + slot;
            while (pv) {
                const int b = __ffs(pv) - 1;
                pv &= pv - 1;
                *op++ = (unsigned short)(n0 + b);
            }
        }
    }
}

__global__ __launch_bounds__(256)
void k_bitmap(const float* __restrict__ B)
{
    const int lane = threadIdx.x & 31;
    const int w    = threadIdx.x >> 5;
    const int m0   = blockIdx.x * 32;
    const int gA   = blockIdx.y * 16 + w * 2;
    const int r0   = lane >> 3;
    const int cq   = lane & 7;

    const float4* bpA = reinterpret_cast<const float4*>(
        B + (size_t)(gA * 32 + r0) * NOUT + m0 + cq * 4);
    const float4* bpB = bpA + (size_t)8 * NOUT;   // group gA+1 starts 32 rows later

    float4 va[8], vb[8];
    #pragma unroll
    for (int i = 0; i < 8; i++) va[i] = __ldg(bpA + (size_t)i * NOUT);
    #pragma unroll
    for (int i = 0; i < 8; i++) vb[i] = __ldg(bpB + (size_t)i * NOUT);

    unsigned p0 = 0, p1 = 0, p2 = 0, p3 = 0;
    unsigned q0 = 0, q1 = 0, q2 = 0, q3 = 0;
    #pragma unroll
    for (int i = 0; i < 8; i++) {
        const unsigned pos = i * 4 + r0;
        p0 |= ((__float_as_uint(va[i].x) >> 23) & 1u) << pos;
        p1 |= ((__float_as_uint(va[i].y) >> 23) & 1u) << pos;
        p2 |= ((__float_as_uint(va[i].z) >> 23) & 1u) << pos;
        p3 |= ((__float_as_uint(va[i].w) >> 23) & 1u) << pos;
        q0 |= ((__float_as_uint(vb[i].x) >> 23) & 1u) << pos;
        q1 |= ((__float_as_uint(vb[i].y) >> 23) & 1u) << pos;
        q2 |= ((__float_as_uint(vb[i].z) >> 23) & 1u) << pos;
        q3 |= ((__float_as_uint(vb[i].w) >> 23) & 1u) << pos;
    }

    const unsigned mm = 0x01010101u << cq;
    p0 = __reduce_or_sync(mm, p0);  p1 = __reduce_or_sync(mm, p1);
    p2 = __reduce_or_sync(mm, p2);  p3 = __reduce_or_sync(mm, p3);
    q0 = __reduce_or_sync(mm, q0);  q1 = __reduce_or_sync(mm, q1);
    q2 = __reduce_or_sync(mm, q2);  q3 = __reduce_or_sync(mm, q3);

    if (r0 == 0) {
        const int colbase = m0 + cq * 4;
        emit_cols(p0, p1, p2, p3, colbase, gA * 32);
        emit_cols(q0, q1, q2, q3, colbase, gA * 32 + 32);
    }
}

// ---------------------------------------------------------------------------
// Kernel 2: warp-uniform sparse gather-max.
// grid = (NOUT/COLT, NROWS/ROWT) = (32, 4), 256 threads, dynamic smem.
// x rows staged in smem (stride XS). Each warp processes column PAIRS:
// lanes 0-15 = rows for col A, lanes 16-31 = rows for col B. Hit indices
// broadcast with __shfl; 16-wide statically unrolled predicated chunks.
// Outputs staged in smem, written back coalesced.
// ---------------------------------------------------------------------------
__global__ __launch_bounds__(256)
void k_pool(const float* __restrict__ x, float* __restrict__ out)
{
    extern __shared__ float dynsmem[];
    float* xs = dynsmem;                    // ROWT * XS
    float* os = dynsmem + ROWT * XS;        // ROWT * OSS

    const int t    = threadIdx.x;
    const int lane = t & 31;
    const int w    = t >> 5;
    const int c0   = blockIdx.x * COLT;
    const int r0   = blockIdx.y * ROWT;

    // Stage ROWT x-rows (64 KB), coalesced LDG.128 -> STS.128
    {
        const float4* x4 = reinterpret_cast<const float4*>(x + (size_t)r0 * NIN);
        #pragma unroll
        for (int i = 0; i < 16; i++) {
            const int qi = t + i * 256;       // 0..4095 float4s
            const int r  = qi >> 8;
            const int q  = qi & 255;
            float4 v = __ldg(x4 + r * 256 + q);
            *reinterpret_cast<float4*>(&xs[r * XS + q * 4]) = v;
        }
    }
    __syncthreads();

    const int half = lane >> 4;             // 0: col A, 1: col B
    const int r    = lane & 15;             // row within tile
    const unsigned full = 0xFFFFFFFFu;

    #pragma unroll 1
    for (int j = 0; j < COLT / 16; j++) {   // 8 pairs per warp
        const int col = c0 + w * 16 + j * 2 + half;
        const int cnt = g_cnt[col];
        const int cntMax = max(__shfl_sync(full, cnt, 0),
                               __shfl_sync(full, cnt, 16));

        float a = (cnt < NIN) ? 0.0f : -__int_as_float(0x7f800000);
        const unsigned short* ip = g_idx + (size_t)col * NIN;

        for (int base = 0; base < cntMax; base += 16) {
            const int s = base + r;
            const int nv = (s < cnt) ? (int)ip[s] : 0;
            #pragma unroll
            for (int k = 0; k < 16; k++) {
                const int n = __shfl_sync(full, nv, k + (half << 4));
                if (base + k < cnt)
                    a = fmaxf(a, xs[r * XS + n]);
            }
        }
        os[r * OSS + (w * 16 + j * 2 + half)] = a;
    }
    __syncthreads();

    // Coalesced writeback: ROWT*COLT floats = 512 float4
    #pragma unroll
    for (int i = 0; i < 2; i++) {
        const int e   = t + i * 256;        // float4 index 0..511
        const int row = e >> 5;             // 32 float4 per row
        const int q   = e & 31;
        float4 v = *reinterpret_cast<const float4*>(&os[row * OSS + q * 4]);
        *reinterpret_cast<float4*>(&out[(size_t)(r0 + row) * NOUT + c0 + q * 4]) = v;
    }
}

// ---------------------------------------------------------------------------
extern "C" void kernel_launch(void* const* d_in, const int* in_sizes, int n_in,
                              void* d_out, int out_size)
{
    const float* x = (const float*)d_in[0];   // (2, 32, 1024) f32
    const float* B = (const float*)d_in[1];   // (1024, 4096) f32, exact 0/1
    float* out     = (float*)d_out;           // (2, 32, 4096) f32
    (void)in_sizes; (void)n_in; (void)out_size;

    const int smem = ROWT * XS * 4 + ROWT * OSS * 4;   // 74240 B
    cudaFuncSetAttribute(k_pool, cudaFuncAttributeMaxDynamicSharedMemorySize, smem);

    k_zero  <<<NOUT / 1024, 1024>>>();
    k_bitmap<<<dim3(NOUT / 32, 2), 256>>>(B);
    k_pool  <<<dim3(NOUT / COLT, NROWS / ROWT), 256, smem>>>(x, out);
}

// round 7
// speedup vs baseline: 1.0996x; 1.0996x over previous
#include <cuda_runtime.h>
#include <cstdint>

#define NIN   1024
#define NOUT  4096
#define NROWS 64            // BATCH*FEAT
#define COLT  64            // columns per k_pool CTA
#define BMS   36            // bitmap smem col stride (words)
#define OSS   65            // output stage row stride (floats), odd -> conflict-free

// Scratch (fully rewritten every launch -> graph-replay deterministic):
__device__ unsigned g_bm[NOUT * 32];      // 512 KB: g_bm[col*32+g] = occupancy bits
__device__ float    g_xT[NIN * NROWS];    // 256 KB: xT[n*64 + row]

// ---------------------------------------------------------------------------
// Kernel 1: scan B (exact 0.0f/1.0f) -> per-column bitmaps; 64 CTAs also
// transpose x into g_xT (tiny, hidden under the DRAM-bound B read).
// grid = (NOUT/32, NIN/512) = (128, 2), 256 threads (8 warps).
// Warp w handles n-groups gA = by*16 + 2w and gA+1; 16 LDG.128 batched.
// Bit = fp32 exponent bit 23 (set for 1.0f, clear for 0.0f).
// ---------------------------------------------------------------------------
__global__ __launch_bounds__(256)
void k_bitmap(const float* __restrict__ B, const float* __restrict__ x)
{
    const int t    = threadIdx.x;
    const int lane = t & 31;
    const int w    = t >> 5;
    const int m0   = blockIdx.x * 32;
    const int gA   = blockIdx.y * 16 + w * 2;
    const int r0   = lane >> 3;
    const int cq   = lane & 7;

    const float4* bpA = reinterpret_cast<const float4*>(
        B + (size_t)(gA * 32 + r0) * NOUT + m0 + cq * 4);
    const float4* bpB = bpA + (size_t)8 * NOUT;   // next group = 32 rows later

    float4 va[8], vb[8];
    #pragma unroll
    for (int i = 0; i < 8; i++) va[i] = __ldg(bpA + (size_t)i * NOUT);
    #pragma unroll
    for (int i = 0; i < 8; i++) vb[i] = __ldg(bpB + (size_t)i * NOUT);

    // x transpose side-job: CTAs (by==0, bx<64) each handle 16 n-values.
    if (blockIdx.y == 0 && blockIdx.x < 64) {
        const int r  = t & 63;
        const int j0 = t >> 6;              // 0..3
        #pragma unroll
        for (int p = 0; p < 4; p++) {
            const int n = blockIdx.x * 16 + j0 * 4 + p;
            g_xT[n * NROWS + r] = __ldg(&x[(size_t)r * NIN + n]);
        }
    }

    unsigned p0 = 0, p1 = 0, p2 = 0, p3 = 0;
    unsigned q0 = 0, q1 = 0, q2 = 0, q3 = 0;
    #pragma unroll
    for (int i = 0; i < 8; i++) {
        const unsigned pos = i * 4 + r0;
        p0 |= ((__float_as_uint(va[i].x) >> 23) & 1u) << pos;
        p1 |= ((__float_as_uint(va[i].y) >> 23) & 1u) << pos;
        p2 |= ((__float_as_uint(va[i].z) >> 23) & 1u) << pos;
        p3 |= ((__float_as_uint(va[i].w) >> 23) & 1u) << pos;
        q0 |= ((__float_as_uint(vb[i].x) >> 23) & 1u) << pos;
        q1 |= ((__float_as_uint(vb[i].y) >> 23) & 1u) << pos;
        q2 |= ((__float_as_uint(vb[i].z) >> 23) & 1u) << pos;
        q3 |= ((__float_as_uint(vb[i].w) >> 23) & 1u) << pos;
    }

    const unsigned mm = 0x01010101u << cq;
    p0 = __reduce_or_sync(mm, p0);  p1 = __reduce_or_sync(mm, p1);
    p2 = __reduce_or_sync(mm, p2);  p3 = __reduce_or_sync(mm, p3);
    q0 = __reduce_or_sync(mm, q0);  q1 = __reduce_or_sync(mm, q1);
    q2 = __reduce_or_sync(mm, q2);  q3 = __reduce_or_sync(mm, q3);

    if (r0 == 0) {
        const int cb = m0 + cq * 4;
        g_bm[(cb + 0) * 32 + gA]     = p0;
        g_bm[(cb + 1) * 32 + gA]     = p1;
        g_bm[(cb + 2) * 32 + gA]     = p2;
        g_bm[(cb + 3) * 32 + gA]     = p3;
        g_bm[(cb + 0) * 32 + gA + 1] = q0;
        g_bm[(cb + 1) * 32 + gA + 1] = q1;
        g_bm[(cb + 2) * 32 + gA + 1] = q2;
        g_bm[(cb + 3) * 32 + gA + 1] = q3;
    }
}

// ---------------------------------------------------------------------------
// Kernel 2: warp-uniform sparse gather-max via transposed x.
// grid = (NOUT/COLT, NROWS/32) = (64, 2), 512 threads (16 warps).
// One WARP processes one COLUMN at a time; lanes = 32 consecutive rows.
// Bit-walk over the column bitmap is identical across lanes (zero divergence);
// each hit n is ONE coalesced 128-byte LDG from g_xT[n*64 + rbase .. +31].
// Static smem only (~17.5 KB).
// ---------------------------------------------------------------------------
__global__ __launch_bounds__(512)
void k_pool(float* __restrict__ out)
{
    __shared__ unsigned bmt[COLT * BMS];    // 9.2 KB bitmap tile
    __shared__ float    os[32 * OSS];       // 8.3 KB output stage

    const int t     = threadIdx.x;
    const int lane  = t & 31;
    const int w     = t >> 5;
    const int c0    = blockIdx.x * COLT;
    const int rbase = blockIdx.y * 32;

    // Stage bitmap tile: 64 cols x 32 words = 8 KB contiguous -> 512 uint4
    {
        uint4 v = __ldg(reinterpret_cast<const uint4*>(g_bm) + blockIdx.x * 512 + t);
        const int c  = t >> 3;
        const int qw = t & 7;
        *reinterpret_cast<uint4*>(&bmt[c * BMS + qw * 4]) = v;
    }
    __syncthreads();

    const float* xTr = g_xT + rbase + lane;

    // Each warp: 4 columns, fully uniform bit-walk
    #pragma unroll 1
    for (int j = 0; j < COLT / 16; j++) {
        const int c = w * 4 + j;
        const unsigned* bp = &bmt[c * BMS];

        float a = -__int_as_float(0x7f800000);   // -inf
        unsigned andall = 0xFFFFFFFFu;

        #pragma unroll
        for (int q = 0; q < 8; q++) {
            uint4 v = *reinterpret_cast<const uint4*>(&bp[q * 4]);  // LDS.128 broadcast
            andall &= v.x & v.y & v.z & v.w;
            unsigned long long w0 = ((unsigned long long)v.y << 32) | v.x;
            unsigned long long w1 = ((unsigned long long)v.w << 32) | v.z;
            const int nb0 = q * 128;
            while (w0) {
                const int b = __ffsll(w0) - 1;
                w0 &= w0 - 1;
                a = fmaxf(a, __ldg(xTr + ((nb0 + b) << 6)));
            }
            while (w1) {
                const int b = __ffsll(w1) - 1;
                w1 &= w1 - 1;
                a = fmaxf(a, __ldg(xTr + ((nb0 + 64 + b) << 6)));
            }
        }

        if (andall != 0xFFFFFFFFu)               // zero participates unless all-ones
            a = fmaxf(a, 0.0f);

        os[lane * OSS + c] = a;                  // odd stride -> conflict-free
    }
    __syncthreads();

    // Coalesced writeback: 32 rows x COLT cols = 2048 floats
    #pragma unroll
    for (int i = 0; i < 4; i++) {
        const int e   = t + i * 512;
        const int row = e >> 6;
        const int c   = e & 63;
        out[(size_t)(rbase + row) * NOUT + c0 + c] = os[row * OSS + c];
    }
}

// ---------------------------------------------------------------------------
extern "C" void kernel_launch(void* const* d_in, const int* in_sizes, int n_in,
                              void* d_out, int out_size)
{
    const float* x = (const float*)d_in[0];   // (2, 32, 1024) f32
    const float* B = (const float*)d_in[1];   // (1024, 4096) f32, exact 0/1
    float* out     = (float*)d_out;           // (2, 32, 4096) f32
    (void)in_sizes; (void)n_in; (void)out_size;

    k_bitmap<<<dim3(NOUT / 32, 2), 256>>>(B, x);
    k_pool  <<<dim3(NOUT / COLT, NROWS / 32), 512>>>(out);
}

// round 8
// speedup vs baseline: 1.7283x; 1.5717x over previous
#include <cuda_runtime.h>
#include <cstdint>

#define NIN   1024
#define NOUT  4096
#define NROWS 64            // BATCH*FEAT
#define COLT  64            // columns per k_pool CTA
#define BMS   36            // bitmap smem col stride (words)
#define ILS   160           // index-list capacity per column (mean nnz=10.2, 20+ sigma safe)
#define OSS   65            // output stage row stride (floats), odd -> conflict-free

// Scratch (fully rewritten every launch -> graph-replay deterministic):
__device__ unsigned g_bm[NOUT * 32];      // 512 KB: g_bm[col*32+g] = occupancy bits
__device__ float    g_xT[NIN * NROWS];    // 256 KB: xT[n*64 + row]

// ---------------------------------------------------------------------------
// Kernel 1: scan B (exact 0.0f/1.0f) -> per-column bitmaps; by==0 CTAs also
// transpose x into g_xT (hidden under the DRAM-bound B read).
// grid = (NOUT/32, NIN/256) = (128, 4), 256 threads; warp = one n-group.
// Bit = fp32 exponent bit 23 (set for 1.0f, clear for 0.0f).
// ---------------------------------------------------------------------------
__global__ __launch_bounds__(256)
void k_bitmap(const float* __restrict__ B, const float* __restrict__ x)
{
    const int t    = threadIdx.x;
    const int lane = t & 31;
    const int w    = t >> 5;
    const int m0   = blockIdx.x * 32;
    const int g    = blockIdx.y * 8 + w;
    const int r0   = lane >> 3;
    const int cq   = lane & 7;

    const float4* bp = reinterpret_cast<const float4*>(
        B + (size_t)(g * 32 + r0) * NOUT + m0 + cq * 4);

    float4 va[8];
    #pragma unroll
    for (int i = 0; i < 8; i++) va[i] = __ldg(bp + (size_t)i * NOUT);

    // x transpose side-job (by==0 only): CTA bx handles n = bx*8 .. bx*8+7.
    if (blockIdx.y == 0) {
        const int r  = t & 63;
        const int nl = t >> 6;          // 0..3
        #pragma unroll
        for (int p = 0; p < 2; p++) {
            const int n = blockIdx.x * 8 + p * 4 + nl;
            g_xT[n * NROWS + r] = __ldg(&x[(size_t)r * NIN + n]);
        }
    }

    unsigned p0 = 0, p1 = 0, p2 = 0, p3 = 0;
    #pragma unroll
    for (int i = 0; i < 8; i++) {
        const unsigned pos = i * 4 + r0;
        p0 |= ((__float_as_uint(va[i].x) >> 23) & 1u) << pos;
        p1 |= ((__float_as_uint(va[i].y) >> 23) & 1u) << pos;
        p2 |= ((__float_as_uint(va[i].z) >> 23) & 1u) << pos;
        p3 |= ((__float_as_uint(va[i].w) >> 23) & 1u) << pos;
    }

    const unsigned mm = 0x01010101u << cq;
    p0 = __reduce_or_sync(mm, p0);  p1 = __reduce_or_sync(mm, p1);
    p2 = __reduce_or_sync(mm, p2);  p3 = __reduce_or_sync(mm, p3);

    if (r0 == 0) {
        const int cb = m0 + cq * 4;
        g_bm[(cb + 0) * 32 + g] = p0;
        g_bm[(cb + 1) * 32 + g] = p1;
        g_bm[(cb + 2) * 32 + g] = p2;
        g_bm[(cb + 3) * 32 + g] = p3;
    }
}

// ---------------------------------------------------------------------------
// Kernel 2: bitmap -> index lists -> batched warp-uniform gather-max.
// grid = (NOUT/COLT, NROWS/32) = (64, 2), 512 threads (16 warps).
// Phase A: stage bitmap tile. Phase B: expand to padded uint16 index lists
// (8 threads/column, shfl prefix-sum; pad to mult of 8 with list[0] -- max is
// idempotent). Phase C: warp per column, lanes = 32 rows; per batch one
// uniform LDS.128 -> 8 independent coalesced LDGs from xT -> 8 FMAX.
// ---------------------------------------------------------------------------
__global__ __launch_bounds__(512)
void k_pool(float* __restrict__ out)
{
    __shared__ unsigned        bmt[COLT * BMS];      // 9.2 KB
    __shared__ unsigned short  ilist[COLT][ILS];     // 20  KB
    __shared__ int             scnt[COLT];
    __shared__ float           os[32 * OSS];         // 8.3 KB

    const int t     = threadIdx.x;
    const int lane  = t & 31;
    const int w     = t >> 5;
    const int c0    = blockIdx.x * COLT;
    const int rbase = blockIdx.y * 32;
    const unsigned full = 0xFFFFFFFFu;

    // -- Phase A: stage bitmap tile (64 cols x 32 words, contiguous in g_bm)
    {
        uint4 v = __ldg(reinterpret_cast<const uint4*>(g_bm) + blockIdx.x * 512 + t);
        const int c  = t >> 3;
        const int qw = t & 7;
        *reinterpret_cast<uint4*>(&bmt[c * BMS + qw * 4]) = v;
    }
    __syncthreads();

    // -- Phase B: expand to index lists (8 threads per column)
    {
        const int cl = lane >> 3;          // column within warp quad
        const int c  = w * 4 + cl;
        const int j  = lane & 7;           // word-quartet 4j..4j+3

        uint4 bv = *reinterpret_cast<const uint4*>(&bmt[c * BMS + j * 4]);
        const int pc = __popc(bv.x) + __popc(bv.y) + __popc(bv.z) + __popc(bv.w);

        // segmented (8-lane) inclusive prefix sum
        int incl = pc;
        #pragma unroll
        for (int d = 1; d < 8; d <<= 1) {
            int v = __shfl_up_sync(full, incl, d);
            if (j >= d) incl += v;
        }
        int off = incl - pc;

        unsigned long long wlo = ((unsigned long long)bv.y << 32) | bv.x;
        unsigned long long whi = ((unsigned long long)bv.w << 32) | bv.z;
        const int nb = j * 128;
        while (wlo) {
            const int b = __ffsll(wlo) - 1;
            wlo &= wlo - 1;
            ilist[c][off++] = (unsigned short)(nb + b);
        }
        while (whi) {
            const int b = __ffsll(whi) - 1;
            whi &= whi - 1;
            ilist[c][off++] = (unsigned short)(nb + 64 + b);
        }
        __syncwarp(full);
        if (j == 7) {                      // thread holding the total
            const int tot = incl;
            scnt[c] = tot;
            if (tot > 0) {
                const unsigned short s0 = ilist[c][0];
                const int padded = (tot + 7) & ~7;
                for (int k = tot; k < padded; k++) ilist[c][k] = s0;
            }
        }
    }
    __syncthreads();

    // -- Phase C: batched gather-max; warp per column, lanes = 32 rows
    const float* xTr = g_xT + rbase + lane;

    #pragma unroll 1
    for (int jj = 0; jj < COLT / 16; jj++) {
        const int c   = w * 4 + jj;
        const int cnt = scnt[c];
        const int nb  = (cnt + 7) >> 3;

        float a0, a1, a2, a3;
        a0 = a1 = a2 = a3 = -__int_as_float(0x7f800000);

        const uint4* lp = reinterpret_cast<const uint4*>(ilist[c]);
        #pragma unroll 1
        for (int b = 0; b < nb; b++) {
            const uint4 v = lp[b];                     // 8 uint16, broadcast
            const int n0 = v.x & 0xFFFF, n1 = v.x >> 16;
            const int n2 = v.y & 0xFFFF, n3 = v.y >> 16;
            const int n4 = v.z & 0xFFFF, n5 = v.z >> 16;
            const int n6 = v.w & 0xFFFF, n7 = v.w >> 16;
            const float l0 = __ldg(xTr + (n0 << 6));
            const float l1 = __ldg(xTr + (n1 << 6));
            const float l2 = __ldg(xTr + (n2 << 6));
            const float l3 = __ldg(xTr + (n3 << 6));
            const float l4 = __ldg(xTr + (n4 << 6));
            const float l5 = __ldg(xTr + (n5 << 6));
            const float l6 = __ldg(xTr + (n6 << 6));
            const float l7 = __ldg(xTr + (n7 << 6));
            a0 = fmaxf(a0, l0);  a1 = fmaxf(a1, l1);
            a2 = fmaxf(a2, l2);  a3 = fmaxf(a3, l3);
            a0 = fmaxf(a0, l4);  a1 = fmaxf(a1, l5);
            a2 = fmaxf(a2, l6);  a3 = fmaxf(a3, l7);
        }

        float a = fmaxf(fmaxf(a0, a1), fmaxf(a2, a3));
        if (cnt < NIN) a = fmaxf(a, 0.0f);   // zero participates unless all-ones
        os[lane * OSS + c] = a;
    }
    __syncthreads();

    // -- Coalesced writeback: 32 rows x 64 cols
    #pragma unroll
    for (int i = 0; i < 4; i++) {
        const int e   = t + i * 512;
        const int row = e >> 6;
        const int c   = e & 63;
        out[(size_t)(rbase + row) * NOUT + c0 + c] = os[row * OSS + c];
    }
}

// ---------------------------------------------------------------------------
extern "C" void kernel_launch(void* const* d_in, const int* in_sizes, int n_in,
                              void* d_out, int out_size)
{
    const float* x = (const float*)d_in[0];   // (2, 32, 1024) f32
    const float* B = (const float*)d_in[1];   // (1024, 4096) f32, exact 0/1
    float* out     = (float*)d_out;           // (2, 32, 4096) f32
    (void)in_sizes; (void)n_in; (void)out_size;

    k_bitmap<<<dim3(NOUT / 32, 4), 256>>>(B, x);
    k_pool  <<<dim3(NOUT / COLT, NROWS / 32), 512>>>(out);
}

// round 10
// speedup vs baseline: 1.7856x; 1.0331x over previous
#include <cuda_runtime.h>
#include <cstdint>

#define NIN   1024
#define NOUT  4096
#define NROWS 64            // BATCH*FEAT
#define BMS   36            // bitmap smem col stride (words)
#define CAP   64            // index-list capacity per col (mean nnz 10.2, ~16 sigma)
#define OSS   33            // output stage row stride (floats)

// Scratch (fully rewritten every launch -> graph-replay deterministic, no atomics):
__device__ unsigned short g_idx[NOUT * CAP];   // 512 KB: padded CSC index lists
__device__ int            g_cnt[NOUT];         // 16 KB
__device__ float          g_xT[NIN * NROWS];   // 256 KB: xT[n*64 + row]

// ---------------------------------------------------------------------------
// Kernel 1: full-column scan of B (exact 0.0f/1.0f) -> padded CSC lists.
// grid = NOUT/32 = 128 CTAs, 512 threads. CTA reads B[:, 32-col tile] (128 KB)
// once: warp w handles n-groups w and w+16 (32 rows each), 16 batched LDG.128
// per lane. Bit = fp32 exponent bit 23. Bitmaps -> smem, then 256 threads
// (8/column) expand to uint16 index lists with a segmented shfl prefix-sum,
// padding each list to a multiple of 8 with its first index (max-idempotent).
// Side-job: transpose x into g_xT.
// ---------------------------------------------------------------------------
__global__ __launch_bounds__(512)
void k_build(const float* __restrict__ B, const float* __restrict__ x)
{
    __shared__ unsigned bmt[32 * BMS];   // 4.6 KB

    const int t    = threadIdx.x;
    const int lane = t & 31;
    const int w    = t >> 5;             // warp 0..15
    const int m0   = blockIdx.x * 32;
    const unsigned full = 0xFFFFFFFFu;

    // x transpose side-job: CTA bx covers n = bx*8 .. bx*8+7, all 64 rows.
    {
        const int r  = t & 63;
        const int nl = t >> 6;           // 0..7
        const int n  = blockIdx.x * 8 + nl;
        g_xT[n * NROWS + r] = __ldg(&x[(size_t)r * NIN + n]);
    }

    // ---- Bitmap build: groups gA = w, gB = w + 16 ----
    {
        const int r0 = lane >> 3;
        const int cq = lane & 7;

        const float4* bpA = reinterpret_cast<const float4*>(
            B + (size_t)(w * 32 + r0) * NOUT + m0 + cq * 4);
        const float4* bpB = bpA + (size_t)128 * NOUT;   // +512 rows

        float4 va[8], vb[8];
        #pragma unroll
        for (int i = 0; i < 8; i++) va[i] = __ldg(bpA + (size_t)i * NOUT);
        #pragma unroll
        for (int i = 0; i < 8; i++) vb[i] = __ldg(bpB + (size_t)i * NOUT);

        unsigned p0 = 0, p1 = 0, p2 = 0, p3 = 0;
        unsigned q0 = 0, q1 = 0, q2 = 0, q3 = 0;
        #pragma unroll
        for (int i = 0; i < 8; i++) {
            const unsigned pos = i * 4 + r0;
            p0 |= ((__float_as_uint(va[i].x) >> 23) & 1u) << pos;
            p1 |= ((__float_as_uint(va[i].y) >> 23) & 1u) << pos;
            p2 |= ((__float_as_uint(va[i].z) >> 23) & 1u) << pos;
            p3 |= ((__float_as_uint(va[i].w) >> 23) & 1u) << pos;
            q0 |= ((__float_as_uint(vb[i].x) >> 23) & 1u) << pos;
            q1 |= ((__float_as_uint(vb[i].y) >> 23) & 1u) << pos;
            q2 |= ((__float_as_uint(vb[i].z) >> 23) & 1u) << pos;
            q3 |= ((__float_as_uint(vb[i].w) >> 23) & 1u) << pos;
        }

        const unsigned mm = 0x01010101u << cq;
        p0 = __reduce_or_sync(mm, p0);  p1 = __reduce_or_sync(mm, p1);
        p2 = __reduce_or_sync(mm, p2);  p3 = __reduce_or_sync(mm, p3);
        q0 = __reduce_or_sync(mm, q0);  q1 = __reduce_or_sync(mm, q1);
        q2 = __reduce_or_sync(mm, q2);  q3 = __reduce_or_sync(mm, q3);

        if (r0 == 0) {
            const int cb = cq * 4;
            bmt[(cb + 0) * BMS + w]      = p0;
            bmt[(cb + 1) * BMS + w]      = p1;
            bmt[(cb + 2) * BMS + w]      = p2;
            bmt[(cb + 3) * BMS + w]      = p3;
            bmt[(cb + 0) * BMS + w + 16] = q0;
            bmt[(cb + 1) * BMS + w + 16] = q1;
            bmt[(cb + 2) * BMS + w + 16] = q2;
            bmt[(cb + 3) * BMS + w + 16] = q3;
        }
    }
    __syncthreads();

    // ---- Index-list expansion: 8 threads per column (threads 0..255) ----
    if (t < 256) {
        const int c = t >> 3;            // local column 0..31
        const int j = t & 7;             // word-quartet 4j..4j+3

        uint4 bv = *reinterpret_cast<const uint4*>(&bmt[c * BMS + j * 4]);
        const int pc = __popc(bv.x) + __popc(bv.y) + __popc(bv.z) + __popc(bv.w);

        // segmented (8-lane) inclusive prefix sum
        int incl = pc;
        #pragma unroll
        for (int d = 1; d < 8; d <<= 1) {
            int v = __shfl_up_sync(full, incl, d);
            if (j >= d) incl += v;
        }
        int off = incl - pc;

        unsigned long long wlo = ((unsigned long long)bv.y << 32) | bv.x;
        unsigned long long whi = ((unsigned long long)bv.w << 32) | bv.z;
        const int nb = j * 128;

        // first index of this lane's span (for padding), min-reduced per segment
        unsigned fi = 0xFFFFu;
        if (wlo)      fi = nb + __ffsll(wlo) - 1;
        else if (whi) fi = nb + 64 + __ffsll(whi) - 1;
        #pragma unroll
        for (int d = 1; d < 8; d <<= 1)
            fi = min(fi, __shfl_xor_sync(full, fi, d));

        const int gcol = blockIdx.x * 32 + c;
        unsigned short* op = g_idx + gcol * CAP;
        while (wlo) {
            const int b = __ffsll(wlo) - 1;
            wlo &= wlo - 1;
            if (off < CAP) op[off] = (unsigned short)(nb + b);
            off++;
        }
        while (whi) {
            const int b = __ffsll(whi) - 1;
            whi &= whi - 1;
            if (off < CAP) op[off] = (unsigned short)(nb + 64 + b);
            off++;
        }
        if (j == 7) {
            int tot = min(incl, CAP);
            g_cnt[gcol] = (incl >= NIN) ? NIN : tot;  // flag all-ones exactly
            if (tot > 0) {
                const int padded = min((tot + 7) & ~7, CAP);
                for (int k = tot; k < padded; k++) op[k] = (unsigned short)fi;
            }
        }
    }
}

// ---------------------------------------------------------------------------
// Kernel 2: pure batched gather-max.
// grid = (NOUT/32, NROWS/32) = (128, 2), 512 threads (16 warps), ~4 KB smem.
// Warp = column, lanes = 32 consecutive rows. Speculatively loads list
// batches 0-1 and issues all 16 gathers before cnt resolves (indices masked
// to stay in-bounds; padded batches are valid under idempotent max).
// ---------------------------------------------------------------------------
__global__ __launch_bounds__(512)
void k_pool(float* __restrict__ out)
{
    __shared__ float os[32 * OSS];       // 4.2 KB

    const int t     = threadIdx.x;
    const int lane  = t & 31;
    const int w     = t >> 5;
    const int c0    = blockIdx.x * 32;
    const int rbase = blockIdx.y * 32;

    const float* xTr = g_xT + rbase + lane;
    const float NEG_INF = -__int_as_float(0x7f800000);

    #pragma unroll
    for (int jc = 0; jc < 2; jc++) {
        const int c = c0 + w * 2 + jc;

        const int cnt = __ldg(&g_cnt[c]);
        const uint4* lp = reinterpret_cast<const uint4*>(g_idx + c * CAP);
        const uint4 u0 = __ldg(lp);          // speculative: always valid memory
        const uint4 u1 = __ldg(lp + 1);

        float a = NEG_INF;
        float v0[8], v1[8];
        {
            const unsigned e[8] = {u0.x & 1023u, (u0.x >> 16) & 1023u,
                                   u0.y & 1023u, (u0.y >> 16) & 1023u,
                                   u0.z & 1023u, (u0.z >> 16) & 1023u,
                                   u0.w & 1023u, (u0.w >> 16) & 1023u};
            #pragma unroll
            for (int k = 0; k < 8; k++) v0[k] = __ldg(xTr + (e[k] << 6));
        }
        {
            const unsigned e[8] = {u1.x & 1023u, (u1.x >> 16) & 1023u,
                                   u1.y & 1023u, (u1.y >> 16) & 1023u,
                                   u1.z & 1023u, (u1.z >> 16) & 1023u,
                                   u1.w & 1023u, (u1.w >> 16) & 1023u};
            #pragma unroll
            for (int k = 0; k < 8; k++) v1[k] = __ldg(xTr + (e[k] << 6));
        }

        const int nb = (min(cnt, CAP) + 7) >> 3;
        if (nb > 0) {
            #pragma unroll
            for (int k = 0; k < 8; k++) a = fmaxf(a, v0[k]);
        }
        if (nb > 1) {
            #pragma unroll
            for (int k = 0; k < 8; k++) a = fmaxf(a, v1[k]);
        }
        #pragma unroll 1
        for (int b = 2; b < nb; b++) {       // rare (cnt > 16)
            const uint4 u = __ldg(lp + b);
            const unsigned e[8] = {u.x & 1023u, (u.x >> 16) & 1023u,
                                   u.y & 1023u, (u.y >> 16) & 1023u,
                                   u.z & 1023u, (u.z >> 16) & 1023u,
                                   u.w & 1023u, (u.w >> 16) & 1023u};
            #pragma unroll
            for (int k = 0; k < 8; k++) a = fmaxf(a, __ldg(xTr + (e[k] << 6)));
        }

        if (cnt < NIN) a = fmaxf(a, 0.0f);   // zero participates unless all-ones
        os[lane * OSS + w * 2 + jc] = a;
    }
    __syncthreads();

    // Coalesced writeback: 32 rows x 32 cols = 1024 floats
    #pragma unroll
    for (int i = 0; i < 2; i++) {
        const int e   = t + i * 512;
        const int row = e >> 5;
        const int c   = e & 31;
        out[(size_t)(rbase + row) * NOUT + c0 + c] = os[row * OSS + c];
    }
}

// ---------------------------------------------------------------------------
extern "C" void kernel_launch(void* const* d_in, const int* in_sizes, int n_in,
                              void* d_out, int out_size)
{
    const float* x = (const float*)d_in[0];   // (2, 32, 1024) f32
    const float* B = (const float*)d_in[1];   // (1024, 4096) f32, exact 0/1
    float* out     = (float*)d_out;           // (2, 32, 4096) f32
    (void)in_sizes; (void)n_in; (void)out_size;

    k_build<<<NOUT / 32, 512>>>(B, x);
    k_pool <<<dim3(NOUT / 32, NROWS / 32), 512>>>(out);
}

// round 12
// speedup vs baseline: 1.8965x; 1.0621x over previous
#include <cuda_runtime.h>
#include <cstdint>

#define NIN   1024
#define NOUT  4096
#define NROWS 64            // BATCH*FEAT
#define BMS   36            // bitmap smem col stride (words)
#define CAP   64            // index-list capacity per col (mean nnz 10.2, ~16 sigma)

// x transposed: xT[n*64 + row]. Rewritten fully every launch.
__device__ float g_xT[NIN * NROWS];   // 256 KB

// ---------------------------------------------------------------------------
// Kernel 1 (tiny): smem-tiled transpose of x -> g_xT. grid (32, 2), block (32, 8).
// ---------------------------------------------------------------------------
__global__ __launch_bounds__(256)
void k_xt(const float* __restrict__ x)
{
    __shared__ float tile[32][33];
    const int n0 = blockIdx.x * 32;
    const int r0 = blockIdx.y * 32;
    const int tx = threadIdx.x, ty = threadIdx.y;

    #pragma unroll
    for (int i = 0; i < 32; i += 8)
        tile[ty + i][tx] = __ldg(&x[(size_t)(r0 + ty + i) * NIN + n0 + tx]);
    __syncthreads();
    #pragma unroll
    for (int i = 0; i < 32; i += 8)
        g_xT[(size_t)(n0 + ty + i) * NROWS + r0 + tx] = tile[tx][ty + i];
}

// ---------------------------------------------------------------------------
// Kernel 2 (fused): B scan -> bitmaps -> smem index lists -> gather-max -> out.
// grid = NOUT/32 = 128 CTAs, 512 threads (16 warps). CTA owns a 32-column tile
// for ALL 1024 n and ALL 64 rows.
//   Phase 1: warp w reads n-groups w and w+16 (16 batched LDG.128/lane, the
//            dominant DRAM cost); bit = fp32 exponent bit 23 (B is exact 0/1).
//   Phase 2: threads 0..255 (8/column) expand bitmaps to padded uint16 lists
//            in smem via segmented shfl prefix-sum (pad with first index).
//   Phase 3: warp w gathers columns 2w, 2w+1 for both 32-row halves: per
//            batch one uniform LDS.128 -> 16 independent coalesced LDGs
//            from L2-resident g_xT -> FMAX.
//   Phase 4: smem-staged coalesced writeback (64 rows x 32 cols).
// ---------------------------------------------------------------------------
__global__ __launch_bounds__(512)
void k_fused(const float* __restrict__ B, float* __restrict__ out)
{
    __shared__ unsigned       bmt[32 * BMS];     // 4.6 KB
    __shared__ unsigned short ilist[32][CAP];    // 4 KB
    __shared__ int            scnt[32];
    __shared__ float          os[64 * 33];       // 8.4 KB

    const int t    = threadIdx.x;
    const int lane = t & 31;
    const int w    = t >> 5;
    const int m0   = blockIdx.x * 32;
    const unsigned full = 0xFFFFFFFFu;

    // ---- Phase 1: bitmap build (groups gA = w, gB = w + 16) ----
    {
        const int r0 = lane >> 3;
        const int cq = lane & 7;

        const float4* bpA = reinterpret_cast<const float4*>(
            B + (size_t)(w * 32 + r0) * NOUT + m0 + cq * 4);
        const float4* bpB = bpA + (size_t)128 * NOUT;   // +512 rows

        float4 va[8], vb[8];
        #pragma unroll
        for (int i = 0; i < 8; i++) va[i] = __ldg(bpA + (size_t)i * NOUT);
        #pragma unroll
        for (int i = 0; i < 8; i++) vb[i] = __ldg(bpB + (size_t)i * NOUT);

        unsigned p0 = 0, p1 = 0, p2 = 0, p3 = 0;
        unsigned q0 = 0, q1 = 0, q2 = 0, q3 = 0;
        #pragma unroll
        for (int i = 0; i < 8; i++) {
            const unsigned pos = i * 4 + r0;
            p0 |= ((__float_as_uint(va[i].x) >> 23) & 1u) << pos;
            p1 |= ((__float_as_uint(va[i].y) >> 23) & 1u) << pos;
            p2 |= ((__float_as_uint(va[i].z) >> 23) & 1u) << pos;
            p3 |= ((__float_as_uint(va[i].w) >> 23) & 1u) << pos;
            q0 |= ((__float_as_uint(vb[i].x) >> 23) & 1u) << pos;
            q1 |= ((__float_as_uint(vb[i].y) >> 23) & 1u) << pos;
            q2 |= ((__float_as_uint(vb[i].z) >> 23) & 1u) << pos;
            q3 |= ((__float_as_uint(vb[i].w) >> 23) & 1u) << pos;
        }

        const unsigned mm = 0x01010101u << cq;
        p0 = __reduce_or_sync(mm, p0);  p1 = __reduce_or_sync(mm, p1);
        p2 = __reduce_or_sync(mm, p2);  p3 = __reduce_or_sync(mm, p3);
        q0 = __reduce_or_sync(mm, q0);  q1 = __reduce_or_sync(mm, q1);
        q2 = __reduce_or_sync(mm, q2);  q3 = __reduce_or_sync(mm, q3);

        if (r0 == 0) {
            const int cb = cq * 4;
            bmt[(cb + 0) * BMS + w]      = p0;
            bmt[(cb + 1) * BMS + w]      = p1;
            bmt[(cb + 2) * BMS + w]      = p2;
            bmt[(cb + 3) * BMS + w]      = p3;
            bmt[(cb + 0) * BMS + w + 16] = q0;
            bmt[(cb + 1) * BMS + w + 16] = q1;
            bmt[(cb + 2) * BMS + w + 16] = q2;
            bmt[(cb + 3) * BMS + w + 16] = q3;
        }
    }
    __syncthreads();

    // ---- Phase 2: list expansion (8 threads per column, threads 0..255) ----
    if (t < 256) {
        const int c = t >> 3;            // local column 0..31
        const int j = t & 7;             // word-quartet 4j..4j+3

        uint4 bv = *reinterpret_cast<const uint4*>(&bmt[c * BMS + j * 4]);
        const int pc = __popc(bv.x) + __popc(bv.y) + __popc(bv.z) + __popc(bv.w);

        int incl = pc;                   // segmented 8-lane inclusive prefix sum
        #pragma unroll
        for (int d = 1; d < 8; d <<= 1) {
            int v = __shfl_up_sync(full, incl, d);
            if (j >= d) incl += v;
        }
        int off = incl - pc;

        unsigned long long wlo = ((unsigned long long)bv.y << 32) | bv.x;
        unsigned long long whi = ((unsigned long long)bv.w << 32) | bv.z;
        const int nb = j * 128;

        unsigned fi = 0xFFFFu;           // first index (for padding)
        if (wlo)      fi = nb + __ffsll(wlo) - 1;
        else if (whi) fi = nb + 64 + __ffsll(whi) - 1;
        #pragma unroll
        for (int d = 1; d < 8; d <<= 1)
            fi = min(fi, __shfl_xor_sync(full, fi, d));

        while (wlo) {
            const int b = __ffsll(wlo) - 1;
            wlo &= wlo - 1;
            if (off < CAP) ilist[c][off] = (unsigned short)(nb + b);
            off++;
        }
        while (whi) {
            const int b = __ffsll(whi) - 1;
            whi &= whi - 1;
            if (off < CAP) ilist[c][off] = (unsigned short)(nb + 64 + b);
            off++;
        }
        if (j == 7) {
            scnt[c] = incl;              // full count (==NIN means all-ones)
            const int tot = min(incl, CAP);
            if (tot > 0) {
                const int padded = min((tot + 7) & ~7, CAP);
                for (int k = tot; k < padded; k++) ilist[c][k] = (unsigned short)fi;
            }
        }
    }
    __syncthreads();

    // ---- Phase 3: gather-max. Warp w: columns 2w, 2w+1; lanes = 32 rows. ----
    {
        const float NEG_INF = -__int_as_float(0x7f800000);
        const int cA = 2 * w, cB = 2 * w + 1;
        const int cntA = scnt[cA], cntB = scnt[cB];
        const int nbA = (min(cntA, CAP) + 7) >> 3;
        const int nbB = (min(cntB, CAP) + 7) >> 3;
        const int nbMax = max(nbA, nbB);

        const uint4* lpA = reinterpret_cast<const uint4*>(ilist[cA]);
        const uint4* lpB = reinterpret_cast<const uint4*>(ilist[cB]);
        const float* xlo = g_xT + lane;          // rows 0..31
        const float* xhi = g_xT + 32 + lane;     // rows 32..63

        float aA0 = NEG_INF, aA1 = NEG_INF, aB0 = NEG_INF, aB1 = NEG_INF;

        #pragma unroll 1
        for (int b = 0; b < nbMax; b++) {
            if (b < nbA) {
                const uint4 u = lpA[b];          // 8 uint16, uniform LDS.128
                const int n[8] = {(int)(u.x & 0xFFFF), (int)(u.x >> 16),
                                  (int)(u.y & 0xFFFF), (int)(u.y >> 16),
                                  (int)(u.z & 0xFFFF), (int)(u.z >> 16),
                                  (int)(u.w & 0xFFFF), (int)(u.w >> 16)};
                #pragma unroll
                for (int k = 0; k < 8; k++) {
                    aA0 = fmaxf(aA0, __ldg(xlo + (n[k] << 6)));
                    aA1 = fmaxf(aA1, __ldg(xhi + (n[k] << 6)));
                }
            }
            if (b < nbB) {
                const uint4 u = lpB[b];
                const int n[8] = {(int)(u.x & 0xFFFF), (int)(u.x >> 16),
                                  (int)(u.y & 0xFFFF), (int)(u.y >> 16),
                                  (int)(u.z & 0xFFFF), (int)(u.z >> 16),
                                  (int)(u.w & 0xFFFF), (int)(u.w >> 16)};
                #pragma unroll
                for (int k = 0; k < 8; k++) {
                    aB0 = fmaxf(aB0, __ldg(xlo + (n[k] << 6)));
                    aB1 = fmaxf(aB1, __ldg(xhi + (n[k] << 6)));
                }
            }
        }

        if (cntA < NIN) { aA0 = fmaxf(aA0, 0.0f); aA1 = fmaxf(aA1, 0.0f); }
        if (cntB < NIN) { aB0 = fmaxf(aB0, 0.0f); aB1 = fmaxf(aB1, 0.0f); }

        os[lane * 33 + cA]        = aA0;
        os[(32 + lane) * 33 + cA] = aA1;
        os[lane * 33 + cB]        = aB0;
        os[(32 + lane) * 33 + cB] = aB1;
    }
    __syncthreads();

    // ---- Phase 4: coalesced writeback (64 rows x 32 cols = 2048 floats) ----
    #pragma unroll
    for (int i = 0; i < 4; i++) {
        const int e   = t + i * 512;
        const int row = e >> 5;
        const int c   = e & 31;
        out[(size_t)row * NOUT + m0 + c] = os[row * 33 + c];
    }
}

// ---------------------------------------------------------------------------
extern "C" void kernel_launch(void* const* d_in, const int* in_sizes, int n_in,
                              void* d_out, int out_size)
{
    const float* x = (const float*)d_in[0];   // (2, 32, 1024) f32
    const float* B = (const float*)d_in[1];   // (1024, 4096) f32, exact 0/1
    float* out     = (float*)d_out;           // (2, 32, 4096) f32
    (void)in_sizes; (void)n_in; (void)out_size;

    k_xt   <<<dim3(32, 2), dim3(32, 8)>>>(x);
    k_fused<<<NOUT / 32, 512>>>(B, out);
}

// round 17
// speedup vs baseline: 2.2233x; 1.1723x over previous
#include <cuda_runtime.h>
#include <cstdint>

#define NIN   1024
#define NOUT  4096
#define NROWS 64            // BATCH*FEAT
#define TC    16            // columns per CTA
#define BMS   36            // bitmap smem col stride (words)
#define CAP   64            // index-list capacity per col (mean nnz 10.2, ~16 sigma)

// x transposed: xT[n*64 + row]. Rewritten fully every launch.
__device__ float g_xT[NIN * NROWS];   // 256 KB

// ---------------------------------------------------------------------------
// Kernel 1 (tiny): smem-tiled transpose of x -> g_xT. grid (32, 2), block (32, 8).
// ---------------------------------------------------------------------------
__global__ __launch_bounds__(256)
void k_xt(const float* __restrict__ x)
{
    __shared__ float tile[32][33];
    const int n0 = blockIdx.x * 32;
    const int r0 = blockIdx.y * 32;
    const int tx = threadIdx.x, ty = threadIdx.y;

    #pragma unroll
    for (int i = 0; i < 32; i += 8)
        tile[ty + i][tx] = __ldg(&x[(size_t)(r0 + ty + i) * NIN + n0 + tx]);
    __syncthreads();
    #pragma unroll
    for (int i = 0; i < 32; i += 8)
        g_xT[(size_t)(n0 + ty + i) * NROWS + r0 + tx] = tile[tx][ty + i];
}

// ---------------------------------------------------------------------------
// Kernel 2 (fused): B scan -> bitmaps -> smem index lists -> gather-max -> out.
// grid = NOUT/TC = 256 CTAs (~2 per SM -> phase overlap across CTAs),
// 512 threads (16 warps). CTA owns a 16-column tile, all 1024 n, all 64 rows.
//   Phase 1: warp w reads n-groups w and w+16; 8 batched LDG.128/lane
//            (32 data regs -> ptxas keeps them in flight). Lane map:
//            cq=lane&3 col-quartet, r0=lane>>2 row-phase. NOTE: float4
//            pointer advance of 2*NOUT elements = 8 rows per step.
//   Phase 2: threads 0..127 (8/column) expand bitmaps to padded uint16
//            lists via segmented shfl prefix-sum (pad with first index).
//   Phase 3: warp w gathers column w (64 rows in 2 halves): per batch one
//            uniform LDS.128 -> 16 independent coalesced LDGs from g_xT.
//   Phase 4: smem-staged coalesced writeback.
// ---------------------------------------------------------------------------
__global__ __launch_bounds__(512)
void k_fused(const float* __restrict__ B, float* __restrict__ out)
{
    __shared__ unsigned       bmt[TC * BMS];     // 2.3 KB
    __shared__ unsigned short ilist[TC][CAP];    // 2 KB
    __shared__ int            scnt[TC];
    __shared__ float          os[64 * 17];       // 4.3 KB

    const int t    = threadIdx.x;
    const int lane = t & 31;
    const int w    = t >> 5;
    const int m0   = blockIdx.x * TC;
    const unsigned full = 0xFFFFFFFFu;

    // ---- Phase 1: bitmap build (groups gA = w, gB = w + 16) ----
    {
        const int r0 = lane >> 2;            // row phase 0..7
        const int cq = lane & 3;             // col quartet 0..3

        const float4* bpA = reinterpret_cast<const float4*>(
            B + (size_t)(w * 32 + r0) * NOUT + m0 + cq * 4);
        const float4* bpB = bpA + (size_t)128 * NOUT;   // +512 rows (float4 elems)

        float4 va[4], vb[4];
        #pragma unroll
        for (int i = 0; i < 4; i++) va[i] = __ldg(bpA + (size_t)(i * 2) * NOUT);  // +8 rows/step
        #pragma unroll
        for (int i = 0; i < 4; i++) vb[i] = __ldg(bpB + (size_t)(i * 2) * NOUT);

        unsigned p0 = 0, p1 = 0, p2 = 0, p3 = 0;
        unsigned q0 = 0, q1 = 0, q2 = 0, q3 = 0;
        #pragma unroll
        for (int i = 0; i < 4; i++) {
            const unsigned pos = i * 8 + r0;
            p0 |= ((__float_as_uint(va[i].x) >> 23) & 1u) << pos;
            p1 |= ((__float_as_uint(va[i].y) >> 23) & 1u) << pos;
            p2 |= ((__float_as_uint(va[i].z) >> 23) & 1u) << pos;
            p3 |= ((__float_as_uint(va[i].w) >> 23) & 1u) << pos;
            q0 |= ((__float_as_uint(vb[i].x) >> 23) & 1u) << pos;
            q1 |= ((__float_as_uint(vb[i].y) >> 23) & 1u) << pos;
            q2 |= ((__float_as_uint(vb[i].z) >> 23) & 1u) << pos;
            q3 |= ((__float_as_uint(vb[i].w) >> 23) & 1u) << pos;
        }

        const unsigned mm = 0x11111111u << cq;   // 8 lanes sharing this quartet
        p0 = __reduce_or_sync(mm, p0);  p1 = __reduce_or_sync(mm, p1);
        p2 = __reduce_or_sync(mm, p2);  p3 = __reduce_or_sync(mm, p3);
        q0 = __reduce_or_sync(mm, q0);  q1 = __reduce_or_sync(mm, q1);
        q2 = __reduce_or_sync(mm, q2);  q3 = __reduce_or_sync(mm, q3);

        if (r0 == 0) {                       // lanes 0..3
            const int cb = cq * 4;
            bmt[(cb + 0) * BMS + w]      = p0;
            bmt[(cb + 1) * BMS + w]      = p1;
            bmt[(cb + 2) * BMS + w]      = p2;
            bmt[(cb + 3) * BMS + w]      = p3;
            bmt[(cb + 0) * BMS + w + 16] = q0;
            bmt[(cb + 1) * BMS + w + 16] = q1;
            bmt[(cb + 2) * BMS + w + 16] = q2;
            bmt[(cb + 3) * BMS + w + 16] = q3;
        }
    }
    __syncthreads();

    // ---- Phase 2: list expansion (8 threads per column, threads 0..127) ----
    if (t < 128) {
        const int c = t >> 3;            // local column 0..15
        const int j = t & 7;             // word-quartet 4j..4j+3

        uint4 bv = *reinterpret_cast<const uint4*>(&bmt[c * BMS + j * 4]);
        const int pc = __popc(bv.x) + __popc(bv.y) + __popc(bv.z) + __popc(bv.w);

        int incl = pc;                   // segmented 8-lane inclusive prefix sum
        #pragma unroll
        for (int d = 1; d < 8; d <<= 1) {
            int v = __shfl_up_sync(full, incl, d);
            if (j >= d) incl += v;
        }
        int off = incl - pc;

        unsigned long long wlo = ((unsigned long long)bv.y << 32) | bv.x;
        unsigned long long whi = ((unsigned long long)bv.w << 32) | bv.z;
        const int nb = j * 128;

        unsigned fi = 0xFFFFu;           // first index (for padding)
        if (wlo)      fi = nb + __ffsll(wlo) - 1;
        else if (whi) fi = nb + 64 + __ffsll(whi) - 1;
        #pragma unroll
        for (int d = 1; d < 8; d <<= 1)
            fi = min(fi, __shfl_xor_sync(full, fi, d));

        while (wlo) {
            const int b = __ffsll(wlo) - 1;
            wlo &= wlo - 1;
            if (off < CAP) ilist[c][off] = (unsigned short)(nb + b);
            off++;
        }
        while (whi) {
            const int b = __ffsll(whi) - 1;
            whi &= whi - 1;
            if (off < CAP) ilist[c][off] = (unsigned short)(nb + 64 + b);
            off++;
        }
        if (j == 7) {
            scnt[c] = incl;              // full count (==NIN means all-ones)
            const int tot = min(incl, CAP);
            if (tot > 0) {
                const int padded = min((tot + 7) & ~7, CAP);
                for (int k = tot; k < padded; k++) ilist[c][k] = (unsigned short)fi;
            }
        }
    }
    __syncthreads();

    // ---- Phase 3: gather-max. Warp w owns column w; lanes = 32 rows. ----
    {
        const float NEG_INF = -__int_as_float(0x7f800000);
        const int cnt = scnt[w];
        const int nb  = (min(cnt, CAP) + 7) >> 3;

        const uint4* lp = reinterpret_cast<const uint4*>(ilist[w]);
        const float* xlo = g_xT + lane;          // rows 0..31
        const float* xhi = g_xT + 32 + lane;     // rows 32..63

        float a0 = NEG_INF, a1 = NEG_INF;

        #pragma unroll 1
        for (int b = 0; b < nb; b++) {
            const uint4 u = lp[b];               // 8 uint16, uniform LDS.128
            const int n[8] = {(int)(u.x & 0xFFFF), (int)(u.x >> 16),
                              (int)(u.y & 0xFFFF), (int)(u.y >> 16),
                              (int)(u.z & 0xFFFF), (int)(u.z >> 16),
                              (int)(u.w & 0xFFFF), (int)(u.w >> 16)};
            #pragma unroll
            for (int k = 0; k < 8; k++) {
                a0 = fmaxf(a0, __ldg(xlo + (n[k] << 6)));
                a1 = fmaxf(a1, __ldg(xhi + (n[k] << 6)));
            }
        }

        if (cnt < NIN) { a0 = fmaxf(a0, 0.0f); a1 = fmaxf(a1, 0.0f); }

        os[lane * 17 + w]        = a0;
        os[(32 + lane) * 17 + w] = a1;
    }
    __syncthreads();

    // ---- Phase 4: coalesced writeback (64 rows x 16 cols = 1024 floats) ----
    #pragma unroll
    for (int i = 0; i < 2; i++) {
        const int e   = t + i * 512;
        const int row = e >> 4;
        const int c   = e & 15;
        out[(size_t)row * NOUT + m0 + c] = os[row * 17 + c];
    }
}

// ---------------------------------------------------------------------------
extern "C" void kernel_launch(void* const* d_in, const int* in_sizes, int n_in,
                              void* d_out, int out_size)
{
    const float* x = (const float*)d_in[0];   // (2, 32, 1024) f32
    const float* B = (const float*)d_in[1];   // (1024, 4096) f32, exact 0/1
    float* out     = (float*)d_out;           // (2, 32, 4096) f32
    (void)in_sizes; (void)n_in; (void)out_size;

    k_xt   <<<dim3(32, 2), dim3(32, 8)>>>(x);
    k_fused<<<NOUT / TC, 512>>>(B, out);
}